// round 9
// baseline (speedup 1.0000x reference)
#include <cuda_runtime.h>
#include <cuda_fp16.h>
#include <cstdint>

#define NMAX 150016
#define EMAX 2400000
#define SCAN_BLK 1024

__device__ int   g_cnt[NMAX];      // in-degree (real edges only)
__device__ int   g_rp[NMAX];       // CSR row_ptr (exclusive scan of cnt)
__device__ int   g_cur[NMAX];      // fill cursors
__device__ int   g_bsum[1024];
__device__ int   g_boff[1024];
__device__ int   g_csr[EMAX];      // src indices bucketed by dst
__device__ float g_dis[NMAX];
__device__ __align__(16) __half g_buf0h[NMAX * 32]; // h' (scaled GEMM output, fp16)
__device__ __align__(16) float  g_buf1[NMAX * 32];  // layer-1 aggregate (fp32)
__device__ __align__(16) float  g_buf2[NMAX * 32];  // layer-2 aggregate (fp32)
__device__ float g_h3[NMAX];

struct alignas(8) half4 { __half2 a, b; };

// ---------------------------------------------------------------- prep

__global__ void cnt_init_k(int N) {
    int i = blockIdx.x * blockDim.x + threadIdx.x;
    if (i < N) g_cnt[i] = 0;
}

__global__ void edge_cnt_k(const int* __restrict__ ei, int E, int N) {
    int e = blockIdx.x * blockDim.x + threadIdx.x;
    if (e >= E) return;
    int d = ei[E + e];
    if ((unsigned)d >= (unsigned)N) d = 0;
    atomicAdd(&g_cnt[d], 1);
}

__global__ void dis_k(int N) {
    int i = blockIdx.x * blockDim.x + threadIdx.x;
    if (i < N) g_dis[i] = rsqrtf((float)(g_cnt[i] + 1));
}

// 3-phase exclusive scan of g_cnt -> g_rp (and g_cur)
__global__ void scan1_k(int N) {
    __shared__ int sh[SCAN_BLK];
    int i = blockIdx.x * SCAN_BLK + threadIdx.x;
    int v = (i < N) ? g_cnt[i] : 0;
    sh[threadIdx.x] = v;
    __syncthreads();
    for (int off = 1; off < SCAN_BLK; off <<= 1) {
        int t = (threadIdx.x >= off) ? sh[threadIdx.x - off] : 0;
        __syncthreads();
        sh[threadIdx.x] += t;
        __syncthreads();
    }
    if (i < N) g_rp[i] = sh[threadIdx.x] - v;   // exclusive
    if (threadIdx.x == SCAN_BLK - 1) g_bsum[blockIdx.x] = sh[threadIdx.x];
}

__global__ void scan2_k(int nb) {
    __shared__ int sh[1024];
    int v = (threadIdx.x < nb) ? g_bsum[threadIdx.x] : 0;
    sh[threadIdx.x] = v;
    __syncthreads();
    for (int off = 1; off < 1024; off <<= 1) {
        int t = (threadIdx.x >= off) ? sh[threadIdx.x - off] : 0;
        __syncthreads();
        sh[threadIdx.x] += t;
        __syncthreads();
    }
    if (threadIdx.x < nb) g_boff[threadIdx.x] = sh[threadIdx.x] - v;  // exclusive
}

__global__ void scan3_k(int N) {
    int i = blockIdx.x * blockDim.x + threadIdx.x;
    if (i < N) {
        int r = g_rp[i] + g_boff[i / SCAN_BLK];
        g_rp[i]  = r;
        g_cur[i] = r;
    }
}

__global__ void fill_k(const int* __restrict__ ei, int E, int N) {
    int e = blockIdx.x * blockDim.x + threadIdx.x;
    if (e >= E) return;
    int s = ei[e];
    int d = ei[E + e];
    if ((unsigned)s >= (unsigned)N) s = 0;
    if ((unsigned)d >= (unsigned)N) d = 0;
    int pos = atomicAdd(&g_cur[d], 1);
    g_csr[pos] = s;
}

// ---------------------------------------------------------------- GEMM (32 out cols)
// 256 threads, tile 128 rows x 32 cols, 4x4 microtile, K chunked by 32,
// double-buffered smem with register prefetch. Output fp16 (h' = h * dis[row]).
// PRE: relu(dis[row]*v + bias[col]) on input.

template <int K, bool PRE>
__global__ void __launch_bounds__(256) gemm_k(
    const float* __restrict__ A, const float* __restrict__ W,
    const float* __restrict__ dis, const float* __restrict__ bias,
    __half* __restrict__ out, int M)
{
    constexpr int NCH = K / 32;
    __shared__ float ws[K][32];
    __shared__ float xs[2][128][33];

    const int tid  = threadIdx.x;
    const int row0 = blockIdx.x * 128;
    const int tx = tid & 7;     // col quad
    const int ty = tid >> 3;    // row quad (0..31)
    const int lr  = tid >> 3;   // loader row
    const int lc4 = tid & 7;    // loader col quad

    for (int i = tid; i < K * 8; i += 256)
        ((float4*)ws)[i] = ((const float4*)W)[i];

    // per-thread chunk slice: 4 rows (lr, lr+32, lr+64, lr+96), col quad lc4
    float4 rv[4];
    auto load_chunk = [&](int kc, float4* r) {
#pragma unroll
        for (int u = 0; u < 4; ++u) {
            int row = row0 + lr + u * 32;
            float4 v = make_float4(0.f, 0.f, 0.f, 0.f);
            if (row < M) {
                v = *(const float4*)(A + (size_t)row * K + kc + lc4 * 4);
                if (PRE) {
                    float dd  = dis[row];
                    float4 bb = *(const float4*)(bias + kc + lc4 * 4);
                    v.x = fmaxf(fmaf(dd, v.x, bb.x), 0.f);
                    v.y = fmaxf(fmaf(dd, v.y, bb.y), 0.f);
                    v.z = fmaxf(fmaf(dd, v.z, bb.z), 0.f);
                    v.w = fmaxf(fmaf(dd, v.w, bb.w), 0.f);
                }
            }
            r[u] = v;
        }
    };
    auto store_chunk = [&](int buf, const float4* r) {
#pragma unroll
        for (int u = 0; u < 4; ++u) {
            xs[buf][lr + u * 32][lc4 * 4 + 0] = r[u].x;
            xs[buf][lr + u * 32][lc4 * 4 + 1] = r[u].y;
            xs[buf][lr + u * 32][lc4 * 4 + 2] = r[u].z;
            xs[buf][lr + u * 32][lc4 * 4 + 3] = r[u].w;
        }
    };

    load_chunk(0, rv);
    store_chunk(0, rv);
    __syncthreads();

    float acc[4][4] = {};

#pragma unroll
    for (int c = 0; c < NCH; ++c) {
        float4 nv[4];
        if (c + 1 < NCH) load_chunk((c + 1) * 32, nv);

        const float (*x)[33] = xs[c & 1];
#pragma unroll
        for (int k = 0; k < 32; ++k) {
            float4 wv = *(const float4*)&ws[c * 32 + k][4 * tx];
            float xr0 = x[4 * ty + 0][k];
            float xr1 = x[4 * ty + 1][k];
            float xr2 = x[4 * ty + 2][k];
            float xr3 = x[4 * ty + 3][k];
            acc[0][0] = fmaf(xr0, wv.x, acc[0][0]);
            acc[0][1] = fmaf(xr0, wv.y, acc[0][1]);
            acc[0][2] = fmaf(xr0, wv.z, acc[0][2]);
            acc[0][3] = fmaf(xr0, wv.w, acc[0][3]);
            acc[1][0] = fmaf(xr1, wv.x, acc[1][0]);
            acc[1][1] = fmaf(xr1, wv.y, acc[1][1]);
            acc[1][2] = fmaf(xr1, wv.z, acc[1][2]);
            acc[1][3] = fmaf(xr1, wv.w, acc[1][3]);
            acc[2][0] = fmaf(xr2, wv.x, acc[2][0]);
            acc[2][1] = fmaf(xr2, wv.y, acc[2][1]);
            acc[2][2] = fmaf(xr2, wv.z, acc[2][2]);
            acc[2][3] = fmaf(xr2, wv.w, acc[2][3]);
            acc[3][0] = fmaf(xr3, wv.x, acc[3][0]);
            acc[3][1] = fmaf(xr3, wv.y, acc[3][1]);
            acc[3][2] = fmaf(xr3, wv.z, acc[3][2]);
            acc[3][3] = fmaf(xr3, wv.w, acc[3][3]);
        }
        if (c + 1 < NCH) {
            __syncthreads();
            store_chunk((c + 1) & 1, nv);
            __syncthreads();
        }
    }

#pragma unroll
    for (int i = 0; i < 4; ++i) {
        int row = row0 + 4 * ty + i;
        if (row < M) {
            float d = dis[row];
            half4 o;
            o.a = __floats2half2_rn(acc[i][0] * d, acc[i][1] * d);
            o.b = __floats2half2_rn(acc[i][2] * d, acc[i][3] * d);
            *(half4*)(out + (size_t)row * 32 + 4 * tx) = o;
        }
    }
}

// ---------------------------------------------------------------- aggregate (warp per node)
// fp16 gathers (64B per edge), fp32 accumulation. acc init = self term h'[node].

__global__ void __launch_bounds__(256) agg_k(
    const __half* __restrict__ h, float* __restrict__ out, int N)
{
    int w    = (blockIdx.x * blockDim.x + threadIdx.x) >> 5;
    int lane = threadIdx.x & 31;
    if (w >= N) return;
    const __half* hp = h + lane;
    int beg = g_rp[w];
    int cnt = g_cnt[w];
    float acc = __half2float(hp[(size_t)w * 32]);
    int j = 0;
    for (; j + 4 <= cnt; j += 4) {
        int s0 = __ldg(&g_csr[beg + j + 0]);
        int s1 = __ldg(&g_csr[beg + j + 1]);
        int s2 = __ldg(&g_csr[beg + j + 2]);
        int s3 = __ldg(&g_csr[beg + j + 3]);
        float v0 = __half2float(__ldg(&hp[(size_t)s0 * 32]));
        float v1 = __half2float(__ldg(&hp[(size_t)s1 * 32]));
        float v2 = __half2float(__ldg(&hp[(size_t)s2 * 32]));
        float v3 = __half2float(__ldg(&hp[(size_t)s3 * 32]));
        acc += (v0 + v1) + (v2 + v3);
    }
    for (; j < cnt; ++j) {
        int s = __ldg(&g_csr[beg + j]);
        acc += __half2float(__ldg(&hp[(size_t)s * 32]));
    }
    out[(size_t)w * 32 + lane] = acc;
}

// ---------------------------------------------------------------- layer 3 (HID -> 1)

__global__ void layer3_k(const float* __restrict__ b2, const float* __restrict__ W3, int N) {
    int g    = blockIdx.x * blockDim.x + threadIdx.x;
    int node = g >> 5;
    int lane = g & 31;
    if (node >= N) return;
    float d = g_dis[node];
    float v = fmaxf(fmaf(d, g_buf2[(size_t)node * 32 + lane], b2[lane]), 0.f) * W3[lane];
#pragma unroll
    for (int o = 16; o; o >>= 1) v += __shfl_xor_sync(0xffffffffu, v, o);
    if (lane == 0) g_h3[node] = v * d;  // h3' = h3 * dis[src]
}

// fused aggregate + sigmoid: lanes split the edge list, butterfly reduce.
__global__ void __launch_bounds__(256) agg3_final_k(
    const float* __restrict__ b3, float* __restrict__ out, int N)
{
    int w    = (blockIdx.x * blockDim.x + threadIdx.x) >> 5;
    int lane = threadIdx.x & 31;
    if (w >= N) return;
    int beg = g_rp[w];
    int cnt = g_cnt[w];
    float acc = 0.f;
    for (int j = lane; j < cnt; j += 32)
        acc += __ldg(&g_h3[__ldg(&g_csr[beg + j])]);
#pragma unroll
    for (int o = 16; o; o >>= 1) acc += __shfl_xor_sync(0xffffffffu, acc, o);
    if (lane == 0) {
        float z = fmaf(g_dis[w], g_h3[w] + acc, b3[0]);
        out[w] = 1.f / (1.f + __expf(-z));
    }
}

// ---------------------------------------------------------------- launch

extern "C" void kernel_launch(void* const* d_in, const int* in_sizes, int n_in,
                              void* d_out, int out_size) {
    const float* x  = (const float*)d_in[0];
    const int*   ei = (const int*)d_in[1];          // int32
    const float* W1 = (const float*)d_in[2];
    const float* b1 = (const float*)d_in[3];
    const float* W2 = (const float*)d_in[4];
    const float* b2 = (const float*)d_in[5];
    const float* W3 = (const float*)d_in[6];
    const float* b3 = (const float*)d_in[7];
    float* out = (float*)d_out;

    const int N = in_sizes[0] / 128;
    const int E = in_sizes[1] / 2;

    void *p0, *p1, *p2, *pdis;
    cudaGetSymbolAddress(&p0, g_buf0h);
    cudaGetSymbolAddress(&p1, g_buf1);
    cudaGetSymbolAddress(&p2, g_buf2);
    cudaGetSymbolAddress(&pdis, g_dis);
    __half* buf0h = (__half*)p0;
    float*  buf1  = (float*)p1;
    float*  buf2  = (float*)p2;
    float*  dis   = (float*)pdis;

    const int T = 256;
    const int nb = (N + SCAN_BLK - 1) / SCAN_BLK;

    // prep: degree count, dis, CSR build
    cnt_init_k<<<(N + T - 1) / T, T>>>(N);
    edge_cnt_k<<<(E + T - 1) / T, T>>>(ei, E, N);
    dis_k<<<(N + T - 1) / T, T>>>(N);
    scan1_k<<<nb, SCAN_BLK>>>(N);
    scan2_k<<<1, 1024>>>(nb);
    scan3_k<<<(N + T - 1) / T, T>>>(N);
    fill_k<<<(E + T - 1) / T, T>>>(ei, E, N);

    const int gemm_blocks = (N + 127) / 128;
    const int agg_blocks  = (N * 32 + T - 1) / T;

    // layer 1
    gemm_k<128, false><<<gemm_blocks, 256>>>(x, W1, dis, nullptr, buf0h, N);
    agg_k<<<agg_blocks, T>>>(buf0h, buf1, N);

    // layer 2 (relu + bias + dis fused into GEMM prologue)
    gemm_k<32, true><<<gemm_blocks, 256>>>(buf1, W2, dis, b1, buf0h, N);
    agg_k<<<agg_blocks, T>>>(buf0h, buf2, N);

    // layer 3
    layer3_k<<<agg_blocks, T>>>(b2, W3, N);
    agg3_final_k<<<agg_blocks, T>>>(b3, out, N);
}

// round 10
// speedup vs baseline: 1.0225x; 1.0225x over previous
#include <cuda_runtime.h>
#include <cuda_fp16.h>
#include <cstdint>

#define NMAX 150016
#define EMAX 2400000
#define SCAN_BLK 1024

__device__ int   g_cnt[NMAX];      // in-degree (real edges only)
__device__ int   g_rp[NMAX];       // CSR row_ptr (exclusive scan of cnt)
__device__ int   g_cur[NMAX];      // fill cursors
__device__ int   g_bsum[1024];
__device__ int   g_boff[1024];
__device__ int   g_csr[EMAX];      // src indices bucketed by dst
__device__ float g_dis[NMAX];
__device__ __align__(16) __half g_buf0h[NMAX * 32]; // h' (scaled, fp16)
__device__ __align__(16) float  g_buf1[NMAX * 32];  // layer-1 aggregate
__device__ __align__(16) float  g_buf2[NMAX * 32];  // layer-2 aggregate
__device__ float g_h3[NMAX];

struct alignas(8) half4 { __half2 a, b; };

// ---------------------------------------------------------------- prep

__global__ void cnt_init_k(int N) {
    int i = blockIdx.x * blockDim.x + threadIdx.x;
    if (i < N) g_cnt[i] = 0;
}

__global__ void edge_cnt_k(const int* __restrict__ ei, int E, int N) {
    int e = blockIdx.x * blockDim.x + threadIdx.x;
    if (e >= E) return;
    int d = ei[E + e];
    if ((unsigned)d >= (unsigned)N) d = 0;
    atomicAdd(&g_cnt[d], 1);
}

// scan phase 1 + dis computation (fused)
__global__ void scan1_k(int N) {
    __shared__ int sh[SCAN_BLK];
    int i = blockIdx.x * SCAN_BLK + threadIdx.x;
    int v = (i < N) ? g_cnt[i] : 0;
    if (i < N) g_dis[i] = rsqrtf((float)(v + 1));
    sh[threadIdx.x] = v;
    __syncthreads();
    for (int off = 1; off < SCAN_BLK; off <<= 1) {
        int t = (threadIdx.x >= off) ? sh[threadIdx.x - off] : 0;
        __syncthreads();
        sh[threadIdx.x] += t;
        __syncthreads();
    }
    if (i < N) g_rp[i] = sh[threadIdx.x] - v;   // exclusive
    if (threadIdx.x == SCAN_BLK - 1) g_bsum[blockIdx.x] = sh[threadIdx.x];
}

__global__ void scan2_k(int nb) {
    __shared__ int sh[1024];
    int v = (threadIdx.x < nb) ? g_bsum[threadIdx.x] : 0;
    sh[threadIdx.x] = v;
    __syncthreads();
    for (int off = 1; off < 1024; off <<= 1) {
        int t = (threadIdx.x >= off) ? sh[threadIdx.x - off] : 0;
        __syncthreads();
        sh[threadIdx.x] += t;
        __syncthreads();
    }
    if (threadIdx.x < nb) g_boff[threadIdx.x] = sh[threadIdx.x] - v;  // exclusive
}

__global__ void scan3_k(int N) {
    int i = blockIdx.x * blockDim.x + threadIdx.x;
    if (i < N) {
        int r = g_rp[i] + g_boff[i / SCAN_BLK];
        g_rp[i]  = r;
        g_cur[i] = r;
    }
}

__global__ void fill_k(const int* __restrict__ ei, int E, int N) {
    int e = blockIdx.x * blockDim.x + threadIdx.x;
    if (e >= E) return;
    int s = ei[e];
    int d = ei[E + e];
    if ((unsigned)s >= (unsigned)N) s = 0;
    if ((unsigned)d >= (unsigned)N) d = 0;
    int pos = atomicAdd(&g_cur[d], 1);
    g_csr[pos] = s;
}

// ---------------------------------------------------------------- GEMM (32 out cols)
// 256 threads, 128x32 tile, 4x4 microtile, K chunked by 32.
// Inner loop in k-quads: 8 LDS.128 per 64 FFMA (~89% FMA density).
// !PRE: cp.async 2-stage pipeline.  PRE: single chunk, fused relu(dis*v+b).
// Epilogue: scale by dis[row], store fp16.

#define MMA4(i, XI, W0, W1, W2, W3)                            \
    acc[i].x = fmaf(XI.x, W0.x, acc[i].x);                     \
    acc[i].y = fmaf(XI.x, W0.y, acc[i].y);                     \
    acc[i].z = fmaf(XI.x, W0.z, acc[i].z);                     \
    acc[i].w = fmaf(XI.x, W0.w, acc[i].w);                     \
    acc[i].x = fmaf(XI.y, W1.x, acc[i].x);                     \
    acc[i].y = fmaf(XI.y, W1.y, acc[i].y);                     \
    acc[i].z = fmaf(XI.y, W1.z, acc[i].z);                     \
    acc[i].w = fmaf(XI.y, W1.w, acc[i].w);                     \
    acc[i].x = fmaf(XI.z, W2.x, acc[i].x);                     \
    acc[i].y = fmaf(XI.z, W2.y, acc[i].y);                     \
    acc[i].z = fmaf(XI.z, W2.z, acc[i].z);                     \
    acc[i].w = fmaf(XI.z, W2.w, acc[i].w);                     \
    acc[i].x = fmaf(XI.w, W3.x, acc[i].x);                     \
    acc[i].y = fmaf(XI.w, W3.y, acc[i].y);                     \
    acc[i].z = fmaf(XI.w, W3.z, acc[i].z);                     \
    acc[i].w = fmaf(XI.w, W3.w, acc[i].w);

template <int K, bool PRE>
__global__ void __launch_bounds__(256) gemm_k(
    const float* __restrict__ A, const float* __restrict__ W,
    const float* __restrict__ dis, const float* __restrict__ bias,
    __half* __restrict__ out, int M)
{
    constexpr int NCH = K / 32;
    constexpr int NBUF = PRE ? 1 : 2;
    constexpr int XST = 36;                 // float stride per row (bank-safe)
    __shared__ float ws[K][32];
    __shared__ float xs[NBUF][128][XST];

    const int tid  = threadIdx.x;
    const int row0 = blockIdx.x * 128;
    const int tx = tid & 7;
    const int ty = tid >> 3;
    const int lr  = tid >> 3;               // loader row 0..31
    const int lc4 = tid & 7;                // loader col-quad

    for (int i = tid; i < K * 8; i += 256)
        ((float4*)ws)[i] = ((const float4*)W)[i];

    float4 acc[4] = {{0,0,0,0},{0,0,0,0},{0,0,0,0},{0,0,0,0}};

    if (!PRE) {
        // cp.async prefetch of a 128x32 chunk
        auto prefetch = [&](int c) {
            int buf = c & 1;
#pragma unroll
            for (int u = 0; u < 4; ++u) {
                int row = row0 + lr + u * 32;
                float* dst = &xs[buf][lr + u * 32][lc4 * 4];
                if (row < M) {
                    unsigned sa = (unsigned)__cvta_generic_to_shared(dst);
                    const float* src = A + (size_t)row * K + c * 32 + lc4 * 4;
                    asm volatile("cp.async.cg.shared.global [%0], [%1], 16;"
                                 :: "r"(sa), "l"(src));
                } else {
                    *(float4*)dst = make_float4(0.f, 0.f, 0.f, 0.f);
                }
            }
            asm volatile("cp.async.commit_group;");
        };

        prefetch(0);
#pragma unroll
        for (int c = 0; c < NCH; ++c) {
            if (c + 1 < NCH) {
                prefetch(c + 1);
                asm volatile("cp.async.wait_group 1;");
            } else {
                asm volatile("cp.async.wait_group 0;");
            }
            __syncthreads();
            const float (*x)[XST] = xs[c & 1];
#pragma unroll
            for (int kq = 0; kq < 8; ++kq) {
                float4 w0 = *(const float4*)&ws[c * 32 + kq * 4 + 0][4 * tx];
                float4 w1 = *(const float4*)&ws[c * 32 + kq * 4 + 1][4 * tx];
                float4 w2 = *(const float4*)&ws[c * 32 + kq * 4 + 2][4 * tx];
                float4 w3 = *(const float4*)&ws[c * 32 + kq * 4 + 3][4 * tx];
                float4 x0 = *(const float4*)&x[4 * ty + 0][kq * 4];
                float4 x1 = *(const float4*)&x[4 * ty + 1][kq * 4];
                float4 x2 = *(const float4*)&x[4 * ty + 2][kq * 4];
                float4 x3 = *(const float4*)&x[4 * ty + 3][kq * 4];
                MMA4(0, x0, w0, w1, w2, w3)
                MMA4(1, x1, w0, w1, w2, w3)
                MMA4(2, x2, w0, w1, w2, w3)
                MMA4(3, x3, w0, w1, w2, w3)
            }
            __syncthreads();
        }
    } else {
        // single chunk (K==32) with fused relu(dis*v + b)
#pragma unroll
        for (int u = 0; u < 4; ++u) {
            int row = row0 + lr + u * 32;
            float4 v = make_float4(0.f, 0.f, 0.f, 0.f);
            if (row < M) {
                v = *(const float4*)(A + (size_t)row * K + lc4 * 4);
                float dd  = dis[row];
                float4 bb = *(const float4*)(bias + lc4 * 4);
                v.x = fmaxf(fmaf(dd, v.x, bb.x), 0.f);
                v.y = fmaxf(fmaf(dd, v.y, bb.y), 0.f);
                v.z = fmaxf(fmaf(dd, v.z, bb.z), 0.f);
                v.w = fmaxf(fmaf(dd, v.w, bb.w), 0.f);
            }
            *(float4*)&xs[0][lr + u * 32][lc4 * 4] = v;
        }
        __syncthreads();
        const float (*x)[XST] = xs[0];
#pragma unroll
        for (int kq = 0; kq < 8; ++kq) {
            float4 w0 = *(const float4*)&ws[kq * 4 + 0][4 * tx];
            float4 w1 = *(const float4*)&ws[kq * 4 + 1][4 * tx];
            float4 w2 = *(const float4*)&ws[kq * 4 + 2][4 * tx];
            float4 w3 = *(const float4*)&ws[kq * 4 + 3][4 * tx];
            float4 x0 = *(const float4*)&x[4 * ty + 0][kq * 4];
            float4 x1 = *(const float4*)&x[4 * ty + 1][kq * 4];
            float4 x2 = *(const float4*)&x[4 * ty + 2][kq * 4];
            float4 x3 = *(const float4*)&x[4 * ty + 3][kq * 4];
            MMA4(0, x0, w0, w1, w2, w3)
            MMA4(1, x1, w0, w1, w2, w3)
            MMA4(2, x2, w0, w1, w2, w3)
            MMA4(3, x3, w0, w1, w2, w3)
        }
    }

#pragma unroll
    for (int i = 0; i < 4; ++i) {
        int row = row0 + 4 * ty + i;
        if (row < M) {
            float d = dis[row];
            half4 o;
            o.a = __floats2half2_rn(acc[i].x * d, acc[i].y * d);
            o.b = __floats2half2_rn(acc[i].z * d, acc[i].w * d);
            *(half4*)(out + (size_t)row * 32 + 4 * tx) = o;
        }
    }
}

// ---------------------------------------------------------------- aggregate (warp per node)
// One coalesced load pulls 32 CSR indices; shfl distributes; gathers 4-deep.

__global__ void __launch_bounds__(256) agg_k(
    const __half* __restrict__ h, float* __restrict__ out, int N)
{
    int w    = (blockIdx.x * blockDim.x + threadIdx.x) >> 5;
    int lane = threadIdx.x & 31;
    if (w >= N) return;
    const __half* hp = h + lane;
    int beg = g_rp[w];
    int cnt = g_cnt[w];
    float a0 = __half2float(hp[(size_t)w * 32]);   // self term
    float a1 = 0.f, a2 = 0.f, a3 = 0.f;
    for (int j = 0; j < cnt; j += 32) {
        int m = cnt - j; if (m > 32) m = 32;
        int idx = (lane < m) ? __ldg(&g_csr[beg + j + lane]) : 0;
        int k = 0;
        for (; k + 4 <= m; k += 4) {
            int s0 = __shfl_sync(0xffffffffu, idx, k + 0);
            int s1 = __shfl_sync(0xffffffffu, idx, k + 1);
            int s2 = __shfl_sync(0xffffffffu, idx, k + 2);
            int s3 = __shfl_sync(0xffffffffu, idx, k + 3);
            a0 += __half2float(__ldg(&hp[(size_t)s0 * 32]));
            a1 += __half2float(__ldg(&hp[(size_t)s1 * 32]));
            a2 += __half2float(__ldg(&hp[(size_t)s2 * 32]));
            a3 += __half2float(__ldg(&hp[(size_t)s3 * 32]));
        }
        for (; k < m; ++k) {
            int s = __shfl_sync(0xffffffffu, idx, k);
            a0 += __half2float(__ldg(&hp[(size_t)s * 32]));
        }
    }
    out[(size_t)w * 32 + lane] = (a0 + a1) + (a2 + a3);
}

// ---------------------------------------------------------------- layer 3 (HID -> 1)

__global__ void layer3_k(const float* __restrict__ b2, const float* __restrict__ W3, int N) {
    int g    = blockIdx.x * blockDim.x + threadIdx.x;
    int node = g >> 5;
    int lane = g & 31;
    if (node >= N) return;
    float d = g_dis[node];
    float v = fmaxf(fmaf(d, g_buf2[(size_t)node * 32 + lane], b2[lane]), 0.f) * W3[lane];
#pragma unroll
    for (int o = 16; o; o >>= 1) v += __shfl_xor_sync(0xffffffffu, v, o);
    if (lane == 0) g_h3[node] = v * d;  // h3' = h3 * dis[src]
}

__global__ void __launch_bounds__(256) agg3_final_k(
    const float* __restrict__ b3, float* __restrict__ out, int N)
{
    int w    = (blockIdx.x * blockDim.x + threadIdx.x) >> 5;
    int lane = threadIdx.x & 31;
    if (w >= N) return;
    int beg = g_rp[w];
    int cnt = g_cnt[w];
    float acc = 0.f;
    for (int j = lane; j < cnt; j += 32)
        acc += __ldg(&g_h3[__ldg(&g_csr[beg + j])]);
#pragma unroll
    for (int o = 16; o; o >>= 1) acc += __shfl_xor_sync(0xffffffffu, acc, o);
    if (lane == 0) {
        float z = fmaf(g_dis[w], g_h3[w] + acc, b3[0]);
        out[w] = 1.f / (1.f + __expf(-z));
    }
}

// ---------------------------------------------------------------- launch

extern "C" void kernel_launch(void* const* d_in, const int* in_sizes, int n_in,
                              void* d_out, int out_size) {
    const float* x  = (const float*)d_in[0];
    const int*   ei = (const int*)d_in[1];          // int32
    const float* W1 = (const float*)d_in[2];
    const float* b1 = (const float*)d_in[3];
    const float* W2 = (const float*)d_in[4];
    const float* b2 = (const float*)d_in[5];
    const float* W3 = (const float*)d_in[6];
    const float* b3 = (const float*)d_in[7];
    float* out = (float*)d_out;

    const int N = in_sizes[0] / 128;
    const int E = in_sizes[1] / 2;

    void *p0, *p1, *p2, *pdis;
    cudaGetSymbolAddress(&p0, g_buf0h);
    cudaGetSymbolAddress(&p1, g_buf1);
    cudaGetSymbolAddress(&p2, g_buf2);
    cudaGetSymbolAddress(&pdis, g_dis);
    __half* buf0h = (__half*)p0;
    float*  buf1  = (float*)p1;
    float*  buf2  = (float*)p2;
    float*  dis   = (float*)pdis;

    const int T = 256;
    const int nb = (N + SCAN_BLK - 1) / SCAN_BLK;

    // prep: degree count, CSR build (dis fused into scan1)
    cnt_init_k<<<(N + T - 1) / T, T>>>(N);
    edge_cnt_k<<<(E + T - 1) / T, T>>>(ei, E, N);
    scan1_k<<<nb, SCAN_BLK>>>(N);
    scan2_k<<<1, 1024>>>(nb);
    scan3_k<<<(N + T - 1) / T, T>>>(N);
    fill_k<<<(E + T - 1) / T, T>>>(ei, E, N);

    const int gemm_blocks = (N + 127) / 128;
    const int agg_blocks  = (N * 32 + T - 1) / T;

    // layer 1
    gemm_k<128, false><<<gemm_blocks, 256>>>(x, W1, dis, nullptr, buf0h, N);
    agg_k<<<agg_blocks, T>>>(buf0h, buf1, N);

    // layer 2 (relu + bias + dis fused into GEMM prologue)
    gemm_k<32, true><<<gemm_blocks, 256>>>(buf1, W2, dis, b1, buf0h, N);
    agg_k<<<agg_blocks, T>>>(buf0h, buf2, N);

    // layer 3
    layer3_k<<<agg_blocks, T>>>(b2, W3, N);
    agg3_final_k<<<agg_blocks, T>>>(b3, out, N);
}